// round 11
// baseline (speedup 1.0000x reference)
#include <cuda_runtime.h>
#include <cuda_bf16.h>

#define N_NODES 50000
#define N_EDGES 600000
#define DIM 128
#define LN_EPS 1e-5f

// ---------------- scratch (static device globals; no allocation) -------------
__device__ float4 g_agg4[N_NODES * (DIM / 4)];   // 25.6 MB aggregation buffer
__device__ float  g_deg_out[N_NODES];
__device__ float  g_deg_in[N_NODES];

// ---------------- f32x2 packed-FMA helpers (Blackwell) -----------------------
__device__ __forceinline__ void unpack2(unsigned long long v, float& a, float& b) {
    asm("mov.b64 {%0, %1}, %2;" : "=f"(a), "=f"(b) : "l"(v));
}
__device__ __forceinline__ void fma2(unsigned long long& d, unsigned long long a,
                                     unsigned long long b) {
    asm("fma.rn.f32x2 %0, %1, %2, %0;" : "+l"(d) : "l"(a), "l"(b));
}

// ---------------- K0: zero agg + degree counters ------------------------------
__global__ void zero_kernel(int nN) {
    int i = blockIdx.x * blockDim.x + threadIdx.x;
    int tot = nN * (DIM / 4);
    if (i < tot) g_agg4[i] = make_float4(0.f, 0.f, 0.f, 0.f);
    if (i < nN) { g_deg_out[i] = 0.f; g_deg_in[i] = 0.f; }
}

// ---------------- K1: degrees --------------------------------------------------
__global__ void degree_kernel(const int* __restrict__ src,
                              const int* __restrict__ dst, int nE) {
    int i = blockIdx.x * blockDim.x + threadIdx.x;
    if (i < nE) {
        atomicAdd(&g_deg_out[src[i]], 1.f);
        atomicAdd(&g_deg_in[dst[i]], 1.f);
    }
}

// ---------------- K2: edge scatter (warp per 2 edges, float4 atomics) ---------
__global__ void __launch_bounds__(256)
scatter_kernel(const float* __restrict__ feat,
               const int* __restrict__ src,
               const int* __restrict__ dst, int nE) {
    int gtid = blockIdx.x * blockDim.x + threadIdx.x;
    int w = gtid >> 5;
    int lane = gtid & 31;
    int e0 = w * 2;
    if (e0 >= nE) return;
    int e1 = e0 + 1;
    bool has1 = (e1 < nE);

    int s0 = __ldg(src + e0);
    int d0 = __ldg(dst + e0);
    int s1 = has1 ? __ldg(src + e1) : s0;
    int d1 = has1 ? __ldg(dst + e1) : d0;

    float ns0 = rsqrtf(fmaxf(__ldg(&g_deg_out[s0]), 1.f));
    float ns1 = rsqrtf(fmaxf(__ldg(&g_deg_out[s1]), 1.f));

    const float4* f4 = reinterpret_cast<const float4*>(feat);
    float4 v0 = __ldcg(f4 + (size_t)s0 * 32 + lane);
    float4 v1 = __ldcg(f4 + (size_t)s1 * 32 + lane);

    v0.x *= ns0; v0.y *= ns0; v0.z *= ns0; v0.w *= ns0;
    atomicAdd(&g_agg4[(size_t)d0 * 32 + lane], v0);
    if (has1) {
        v1.x *= ns1; v1.y *= ns1; v1.z *= ns1; v1.w *= ns1;
        atomicAdd(&g_agg4[(size_t)d1 * 32 + lane], v1);
    }
}

// ---------------- K3: fused GEMM + bias/scale + LN + ReLU ---------------------
// K-axis f32x2 packing: x pairs (k even, k odd) come free from the natural smem
// row layout (one LDS.128 = 2 packed pairs); W pre-packed in smem as
// w2[k2][c] = (W[2k2][c], W[2k2+1][c]). No pack MOVs in the mainloop.
// 640 threads = 20 warps x 4 nodes = 80 nodes/block; 625 blocks, no tail.
// Lane owns output cols {lane, lane+32, lane+64, lane+96}.
// smem: W-packed 128KB + x staging [80x256] 80KB = 208KB.
__global__ void __launch_bounds__(640, 1)
final_kernel(const float* __restrict__ feat,
             const float* __restrict__ fc_w, const float* __restrict__ fc_b,
             const float* __restrict__ res_w,
             const float* __restrict__ ln_g, const float* __restrict__ ln_b,
             float* __restrict__ out, int nN) {
    extern __shared__ float smem_f[];
    float2* wpk = reinterpret_cast<float2*>(smem_f);  // [128 k2][128 c] = 128 KB
    float*  xs  = smem_f + 32768;                      // 80*256 floats = 80 KB

    int tid = threadIdx.x;
    // --- pack W (fc_w rows k<128, res_w rows k>=128) into k-pair float2s ---
    for (int i = tid; i < 16384; i += 640) {
        int k2 = i >> 7, c = i & 127;
        int k0 = 2 * k2;
        float a0, a1;
        if (k0 < 128) {
            a0 = __ldg(fc_w + k0 * 128 + c);
            a1 = __ldg(fc_w + (k0 + 1) * 128 + c);
        } else {
            a0 = __ldg(res_w + (k0 - 128) * 128 + c);
            a1 = __ldg(res_w + (k0 - 127) * 128 + c);
        }
        wpk[i] = make_float2(a0, a1);
    }

    int lane = tid & 31;
    int warp = tid >> 5;
    int v0 = blockIdx.x * 80 + warp * 4;

    const float4* ga4 = g_agg4;
    const float4* ft4 = reinterpret_cast<const float4*>(feat);
    float* xw = xs + warp * 4 * 256;   // this warp's 4 node rows

    // --- stage x = [in_norm*agg(128) ; feat(128)] for 4 nodes ---
    float inrm[4];
#pragma unroll
    for (int n = 0; n < 4; n++) {
        int v = min(v0 + n, nN - 1);
        float t = rsqrtf(fmaxf(__ldg(&g_deg_in[v]), 1.f));
        inrm[n] = t;
        float4 a = __ldcg(ga4 + (size_t)v * 32 + lane);
        a.x *= t; a.y *= t; a.z *= t; a.w *= t;
        float* row = xw + n * 256;
        reinterpret_cast<float4*>(row)[lane]       = a;
        reinterpret_cast<float4*>(row + 128)[lane] = __ldg(ft4 + (size_t)v * 32 + lane);
    }
    __syncthreads();   // W pack + x staging both complete

    // --- mainloop: per k4 (4 k-values = 2 packed k-pairs) ---
    unsigned long long acc[4][4];
#pragma unroll
    for (int n = 0; n < 4; n++)
#pragma unroll
        for (int c = 0; c < 4; c++) acc[n][c] = 0ull;

    const unsigned long long* wp =
        reinterpret_cast<const unsigned long long*>(wpk);

#pragma unroll 2
    for (int k4 = 0; k4 < 64; k4++) {
        ulonglong2 xq[4];
#pragma unroll
        for (int n = 0; n < 4; n++)
            xq[n] = reinterpret_cast<const ulonglong2*>(xw + n * 256)[k4]; // bcast

        int ka = (2 * k4) * 128 + lane;
        unsigned long long wa[4], wb[4];
#pragma unroll
        for (int c = 0; c < 4; c++) {
            wa[c] = wp[ka + 32 * c];          // k-pair (4k4, 4k4+1)
            wb[c] = wp[ka + 128 + 32 * c];    // k-pair (4k4+2, 4k4+3)
        }
#pragma unroll
        for (int n = 0; n < 4; n++) {
#pragma unroll
            for (int c = 0; c < 4; c++) {
                fma2(acc[n][c], xq[n].x, wa[c]);
                fma2(acc[n][c], xq[n].y, wb[c]);
            }
        }
    }

    // --- epilogue: fold pairs, bias, LayerNorm, ReLU, store ---
    float bsc[4], gsc[4], bbs[4];
#pragma unroll
    for (int c = 0; c < 4; c++) {
        bsc[c] = __ldg(fc_b + lane + 32 * c);
        gsc[c] = __ldg(ln_g + lane + 32 * c);
        bbs[c] = __ldg(ln_b + lane + 32 * c);
    }

#pragma unroll
    for (int n = 0; n < 4; n++) {
        float y[4];
#pragma unroll
        for (int c = 0; c < 4; c++) {
            float lo, hi;
            unpack2(acc[n][c], lo, hi);
            y[c] = lo + hi + inrm[n] * bsc[c];
        }

        float s = y[0] + y[1] + y[2] + y[3];
#pragma unroll
        for (int o = 16; o > 0; o >>= 1) s += __shfl_xor_sync(0xffffffffu, s, o);
        float mu = s * (1.0f / 128.0f);

        float d[4];
        float ss = 0.f;
#pragma unroll
        for (int c = 0; c < 4; c++) { d[c] = y[c] - mu; ss += d[c] * d[c]; }
#pragma unroll
        for (int o = 16; o > 0; o >>= 1) ss += __shfl_xor_sync(0xffffffffu, ss, o);
        float rs = rsqrtf(ss * (1.0f / 128.0f) + LN_EPS);

        int v = v0 + n;
        if (v < nN) {
            float* orow = out + (size_t)v * DIM;
#pragma unroll
            for (int c = 0; c < 4; c++)
                orow[lane + 32 * c] = fmaxf(fmaf(d[c] * rs, gsc[c], bbs[c]), 0.f);
        }
    }
}

// ---------------- launcher -----------------------------------------------------
extern "C" void kernel_launch(void* const* d_in, const int* in_sizes, int n_in,
                              void* d_out, int out_size) {
    const float* feat  = (const float*)d_in[0];
    const int*   src   = (const int*)d_in[1];
    const int*   dst   = (const int*)d_in[2];
    const float* fc_w  = (const float*)d_in[3];
    const float* fc_b  = (const float*)d_in[4];
    const float* res_w = (const float*)d_in[5];
    const float* ln_g  = (const float*)d_in[6];
    const float* ln_b  = (const float*)d_in[7];
    float* out = (float*)d_out;

    int nN = in_sizes[0] / DIM;   // 50000
    int nE = in_sizes[1];         // 600000

    // K0: zero agg + degree counters
    {
        int tot = nN * (DIM / 4);
        zero_kernel<<<(tot + 255) / 256, 256>>>(nN);
    }
    // K1: degrees
    degree_kernel<<<(nE + 255) / 256, 256>>>(src, dst, nE);
    // K2: scatter-add of normalized source features (warp per 2 edges)
    {
        long long warps = ((long long)nE + 1) / 2;
        long long threads = warps * 32;
        int blocks = (int)((threads + 255) / 256);
        scatter_kernel<<<blocks, 256>>>(feat, src, dst, nE);
    }
    // K3: fused GEMM + bias + in_norm scale + residual + LN + ReLU
    {
        const int SMEM = (32768 + 20480) * 4;  // 208 KB
        cudaFuncSetAttribute(final_kernel,
                             cudaFuncAttributeMaxDynamicSharedMemorySize, SMEM);
        int blocks = (nN + 79) / 80;           // 625, exact
        final_kernel<<<blocks, 640, SMEM>>>(feat, fc_w, fc_b, res_w, ln_g, ln_b,
                                            out, nN);
    }
}

// round 12
// speedup vs baseline: 1.0736x; 1.0736x over previous
#include <cuda_runtime.h>
#include <cuda_bf16.h>

#define N_NODES 50000
#define N_EDGES 600000
#define DIM 128
#define LN_EPS 1e-5f

// ---------------- scratch (static device globals; no allocation) -------------
__device__ float4 g_agg4[N_NODES * (DIM / 4)];   // 25.6 MB aggregation buffer
__device__ float  g_deg_out[N_NODES];
__device__ float  g_deg_in[N_NODES];

// ---------------- f32x2 packed-FMA helpers (Blackwell) -----------------------
__device__ __forceinline__ void unpack2(unsigned long long v, float& a, float& b) {
    asm("mov.b64 {%0, %1}, %2;" : "=f"(a), "=f"(b) : "l"(v));
}
__device__ __forceinline__ void fma2(unsigned long long& d, unsigned long long a,
                                     unsigned long long b) {
    asm("fma.rn.f32x2 %0, %1, %2, %0;" : "+l"(d) : "l"(a), "l"(b));
}

// ---------------- K0: zero agg + degree counters ------------------------------
__global__ void zero_kernel(int nN) {
    int i = blockIdx.x * blockDim.x + threadIdx.x;
    int tot = nN * (DIM / 4);
    if (i < tot) g_agg4[i] = make_float4(0.f, 0.f, 0.f, 0.f);
    if (i < nN) { g_deg_out[i] = 0.f; g_deg_in[i] = 0.f; }
}

// ---------------- K1: degrees --------------------------------------------------
__global__ void degree_kernel(const int* __restrict__ src,
                              const int* __restrict__ dst, int nE) {
    int i = blockIdx.x * blockDim.x + threadIdx.x;
    if (i < nE) {
        atomicAdd(&g_deg_out[src[i]], 1.f);
        atomicAdd(&g_deg_in[dst[i]], 1.f);
    }
}

// ---------------- K2: edge scatter (warp per 2 edges, float4 atomics) ---------
__global__ void __launch_bounds__(256)
scatter_kernel(const float* __restrict__ feat,
               const int* __restrict__ src,
               const int* __restrict__ dst, int nE) {
    int gtid = blockIdx.x * blockDim.x + threadIdx.x;
    int w = gtid >> 5;
    int lane = gtid & 31;
    int e0 = w * 2;
    if (e0 >= nE) return;
    int e1 = e0 + 1;
    bool has1 = (e1 < nE);

    int s0 = __ldg(src + e0);
    int d0 = __ldg(dst + e0);
    int s1 = has1 ? __ldg(src + e1) : s0;
    int d1 = has1 ? __ldg(dst + e1) : d0;

    float ns0 = rsqrtf(fmaxf(__ldg(&g_deg_out[s0]), 1.f));
    float ns1 = rsqrtf(fmaxf(__ldg(&g_deg_out[s1]), 1.f));

    const float4* f4 = reinterpret_cast<const float4*>(feat);
    float4 v0 = __ldcg(f4 + (size_t)s0 * 32 + lane);
    float4 v1 = __ldcg(f4 + (size_t)s1 * 32 + lane);

    v0.x *= ns0; v0.y *= ns0; v0.z *= ns0; v0.w *= ns0;
    atomicAdd(&g_agg4[(size_t)d0 * 32 + lane], v0);
    if (has1) {
        v1.x *= ns1; v1.y *= ns1; v1.z *= ns1; v1.w *= ns1;
        atomicAdd(&g_agg4[(size_t)d1 * 32 + lane], v1);
    }
}

// ---------------- K3: fused GEMM + bias/scale + LN + ReLU ---------------------
// K-axis f32x2 packing, conflict-free W layout.
// W smem layout: ulonglong2 entries indexed (k2*2 + c2)*32 + lane, where entry
//   .x = (W[2k2][lane+64*c2],      W[2k2+1][lane+64*c2])        (col c = 2*c2)
//   .y = (W[2k2][lane+32+64*c2],   W[2k2+1][lane+32+64*c2])     (col c = 2*c2+1)
// Consecutive lanes read consecutive 16B -> zero bank conflicts.
// x staged in natural k order; one LDS.128 broadcast yields 2 packed k-pairs.
// 512 threads = 16 warps x 6 nodes = 96 nodes/block; lane owns cols lane+32c.
// smem: W 128KB + x [96x256] 96KB = 224KB.
__global__ void __launch_bounds__(512, 1)
final_kernel(const float* __restrict__ feat,
             const float* __restrict__ fc_w, const float* __restrict__ fc_b,
             const float* __restrict__ res_w,
             const float* __restrict__ ln_g, const float* __restrict__ ln_b,
             float* __restrict__ out, int nN) {
    extern __shared__ float smem_f[];
    float2* wpk = reinterpret_cast<float2*>(smem_f);   // 16384 float2 = 128 KB
    float*  xs  = smem_f + 32768;                      // 96*256 floats = 96 KB

    int tid = threadIdx.x;
    // --- pack W into k-pair float2s, [k2][c2][lane][j] layout ---
    for (int i = tid; i < 16384; i += 512) {
        int k2 = i >> 7;
        int c2 = (i >> 6) & 1;
        int ln = (i >> 1) & 31;
        int j  = i & 1;
        int col = ln + 32 * (2 * c2 + j);
        int k0 = 2 * k2;
        float a0, a1;
        if (k0 < 128) {
            a0 = __ldg(fc_w + k0 * 128 + col);
            a1 = __ldg(fc_w + (k0 + 1) * 128 + col);
        } else {
            a0 = __ldg(res_w + (k0 - 128) * 128 + col);
            a1 = __ldg(res_w + (k0 - 127) * 128 + col);
        }
        wpk[i] = make_float2(a0, a1);
    }

    int lane = tid & 31;
    int warp = tid >> 5;
    int v0 = blockIdx.x * 96 + warp * 6;
    if (v0 >= nN) { __syncthreads(); return; }

    const float4* ga4 = g_agg4;
    const float4* ft4 = reinterpret_cast<const float4*>(feat);
    float* xw = xs + warp * 6 * 256;   // this warp's 6 node rows

    // --- stage x = [in_norm*agg(128) ; feat(128)] for 6 nodes, natural k order
    float inrm[6];
#pragma unroll
    for (int n = 0; n < 6; n++) {
        int v = min(v0 + n, nN - 1);
        float t = rsqrtf(fmaxf(__ldg(&g_deg_in[v]), 1.f));
        inrm[n] = t;
        float4 a = __ldcg(ga4 + (size_t)v * 32 + lane);
        a.x *= t; a.y *= t; a.z *= t; a.w *= t;
        float* row = xw + n * 256;
        reinterpret_cast<float4*>(row)[lane]       = a;
        reinterpret_cast<float4*>(row + 128)[lane] = __ldg(ft4 + (size_t)v * 32 + lane);
    }
    __syncthreads();   // W pack + x staging complete

    // --- mainloop ---
    unsigned long long acc[6][4];
#pragma unroll
    for (int n = 0; n < 6; n++)
#pragma unroll
        for (int c = 0; c < 4; c++) acc[n][c] = 0ull;

    const ulonglong2* wp2 = reinterpret_cast<const ulonglong2*>(wpk);

#pragma unroll 2
    for (int k4 = 0; k4 < 64; k4++) {
        ulonglong2 xq[6];
#pragma unroll
        for (int n = 0; n < 6; n++)
            xq[n] = reinterpret_cast<const ulonglong2*>(xw + n * 256)[k4]; // bcast

        int ia = 128 * k4 + lane;
        ulonglong2 wA0 = wp2[ia];         // k2=2k4,   cols {lane, lane+32}
        ulonglong2 wA1 = wp2[ia + 32];    // k2=2k4,   cols {lane+64, lane+96}
        ulonglong2 wB0 = wp2[ia + 64];    // k2=2k4+1, cols {lane, lane+32}
        ulonglong2 wB1 = wp2[ia + 96];    // k2=2k4+1, cols {lane+64, lane+96}

#pragma unroll
        for (int n = 0; n < 6; n++) {
            fma2(acc[n][0], xq[n].x, wA0.x);
            fma2(acc[n][1], xq[n].x, wA0.y);
            fma2(acc[n][2], xq[n].x, wA1.x);
            fma2(acc[n][3], xq[n].x, wA1.y);
            fma2(acc[n][0], xq[n].y, wB0.x);
            fma2(acc[n][1], xq[n].y, wB0.y);
            fma2(acc[n][2], xq[n].y, wB1.x);
            fma2(acc[n][3], xq[n].y, wB1.y);
        }
    }

    // --- epilogue: fold even/odd halves, bias, LayerNorm, ReLU, store ---
    float bsc[4], gsc[4], bbs[4];
#pragma unroll
    for (int c = 0; c < 4; c++) {
        bsc[c] = __ldg(fc_b + lane + 32 * c);
        gsc[c] = __ldg(ln_g + lane + 32 * c);
        bbs[c] = __ldg(ln_b + lane + 32 * c);
    }

#pragma unroll
    for (int n = 0; n < 6; n++) {
        float y[4];
#pragma unroll
        for (int c = 0; c < 4; c++) {
            float lo, hi;
            unpack2(acc[n][c], lo, hi);
            y[c] = lo + hi + inrm[n] * bsc[c];
        }

        float s = y[0] + y[1] + y[2] + y[3];
#pragma unroll
        for (int o = 16; o > 0; o >>= 1) s += __shfl_xor_sync(0xffffffffu, s, o);
        float mu = s * (1.0f / 128.0f);

        float d[4];
        float ss = 0.f;
#pragma unroll
        for (int c = 0; c < 4; c++) { d[c] = y[c] - mu; ss += d[c] * d[c]; }
#pragma unroll
        for (int o = 16; o > 0; o >>= 1) ss += __shfl_xor_sync(0xffffffffu, ss, o);
        float rs = rsqrtf(ss * (1.0f / 128.0f) + LN_EPS);

        int v = v0 + n;
        if (v < nN) {
            float* orow = out + (size_t)v * DIM;
#pragma unroll
            for (int c = 0; c < 4; c++)
                orow[lane + 32 * c] = fmaxf(fmaf(d[c] * rs, gsc[c], bbs[c]), 0.f);
        }
    }
}

// ---------------- launcher -----------------------------------------------------
extern "C" void kernel_launch(void* const* d_in, const int* in_sizes, int n_in,
                              void* d_out, int out_size) {
    const float* feat  = (const float*)d_in[0];
    const int*   src   = (const int*)d_in[1];
    const int*   dst   = (const int*)d_in[2];
    const float* fc_w  = (const float*)d_in[3];
    const float* fc_b  = (const float*)d_in[4];
    const float* res_w = (const float*)d_in[5];
    const float* ln_g  = (const float*)d_in[6];
    const float* ln_b  = (const float*)d_in[7];
    float* out = (float*)d_out;

    int nN = in_sizes[0] / DIM;   // 50000
    int nE = in_sizes[1];         // 600000

    // K0: zero agg + degree counters
    {
        int tot = nN * (DIM / 4);
        zero_kernel<<<(tot + 255) / 256, 256>>>(nN);
    }
    // K1: degrees
    degree_kernel<<<(nE + 255) / 256, 256>>>(src, dst, nE);
    // K2: scatter-add of normalized source features (warp per 2 edges)
    {
        long long warps = ((long long)nE + 1) / 2;
        long long threads = warps * 32;
        int blocks = (int)((threads + 255) / 256);
        scatter_kernel<<<blocks, 256>>>(feat, src, dst, nE);
    }
    // K3: fused GEMM + bias + in_norm scale + residual + LN + ReLU
    {
        const int SMEM = (32768 + 24576) * 4;  // 224 KB
        cudaFuncSetAttribute(final_kernel,
                             cudaFuncAttributeMaxDynamicSharedMemorySize, SMEM);
        int blocks = (nN + 95) / 96;           // 521
        final_kernel<<<blocks, 512, SMEM>>>(feat, fc_w, fc_b, res_w, ln_g, ln_b,
                                            out, nN);
    }
}

// round 15
// speedup vs baseline: 1.4981x; 1.3954x over previous
#include <cuda_runtime.h>
#include <cuda_bf16.h>
#include <cstdint>

#define N_NODES 50000
#define N_EDGES 600000
#define DIM 128
#define LN_EPS 1e-5f

// ---------------- scratch (static device globals; no allocation) -------------
__device__ float4 g_agg4[N_NODES * (DIM / 4)];   // 25.6 MB aggregation buffer
__device__ float  g_deg_out[N_NODES];
__device__ float  g_deg_in[N_NODES];

// ---------------- K0: zero agg + degree counters ------------------------------
__global__ void zero_kernel(int nN) {
    int i = blockIdx.x * blockDim.x + threadIdx.x;
    int tot = nN * (DIM / 4);
    if (i < tot) g_agg4[i] = make_float4(0.f, 0.f, 0.f, 0.f);
    if (i < nN) { g_deg_out[i] = 0.f; g_deg_in[i] = 0.f; }
}

// ---------------- K1: degrees --------------------------------------------------
__global__ void degree_kernel(const int* __restrict__ src,
                              const int* __restrict__ dst, int nE) {
    int i = blockIdx.x * blockDim.x + threadIdx.x;
    if (i < nE) {
        atomicAdd(&g_deg_out[src[i]], 1.f);
        atomicAdd(&g_deg_in[dst[i]], 1.f);
    }
}

// ---------------- K2: edge scatter (warp per 2 edges, float4 atomics) ---------
__global__ void __launch_bounds__(256)
scatter_kernel(const float* __restrict__ feat,
               const int* __restrict__ src,
               const int* __restrict__ dst, int nE) {
    int gtid = blockIdx.x * blockDim.x + threadIdx.x;
    int w = gtid >> 5;
    int lane = gtid & 31;
    int e0 = w * 2;
    if (e0 >= nE) return;
    int e1 = e0 + 1;
    bool has1 = (e1 < nE);

    int s0 = __ldg(src + e0);
    int d0 = __ldg(dst + e0);
    int s1 = has1 ? __ldg(src + e1) : s0;
    int d1 = has1 ? __ldg(dst + e1) : d0;

    float ns0 = rsqrtf(fmaxf(__ldg(&g_deg_out[s0]), 1.f));
    float ns1 = rsqrtf(fmaxf(__ldg(&g_deg_out[s1]), 1.f));

    const float4* f4 = reinterpret_cast<const float4*>(feat);
    float4 v0 = __ldcg(f4 + (size_t)s0 * 32 + lane);
    float4 v1 = __ldcg(f4 + (size_t)s1 * 32 + lane);

    v0.x *= ns0; v0.y *= ns0; v0.z *= ns0; v0.w *= ns0;
    atomicAdd(&g_agg4[(size_t)d0 * 32 + lane], v0);
    if (has1) {
        v1.x *= ns1; v1.y *= ns1; v1.z *= ns1; v1.w *= ns1;
        atomicAdd(&g_agg4[(size_t)d1 * 32 + lane], v1);
    }
}

// ================= mma.sync helpers (sm_80+ HMMA, no 'a'-gating) ==============
__device__ __forceinline__ uint32_t smem_u32(const void* p) {
    uint32_t a;
    asm("{ .reg .u64 t; cvta.to.shared.u64 t, %1; cvt.u32.u64 %0, t; }"
        : "=r"(a) : "l"(p));
    return a;
}

__device__ __forceinline__ void ldmx4(uint32_t r[4], uint32_t addr) {
    asm volatile("ldmatrix.sync.aligned.m8n8.x4.shared.b16 {%0,%1,%2,%3}, [%4];"
                 : "=r"(r[0]), "=r"(r[1]), "=r"(r[2]), "=r"(r[3]) : "r"(addr));
}
__device__ __forceinline__ void ldmx4t(uint32_t r[4], uint32_t addr) {
    asm volatile("ldmatrix.sync.aligned.m8n8.x4.trans.shared.b16 {%0,%1,%2,%3}, [%4];"
                 : "=r"(r[0]), "=r"(r[1]), "=r"(r[2]), "=r"(r[3]) : "r"(addr));
}
__device__ __forceinline__ void mma16816(float* d, const uint32_t* a,
                                         uint32_t b0, uint32_t b1) {
    asm volatile(
        "mma.sync.aligned.m16n8k16.row.col.f32.bf16.bf16.f32 "
        "{%0,%1,%2,%3}, {%4,%5,%6,%7}, {%8,%9}, {%0,%1,%2,%3};"
        : "+f"(d[0]), "+f"(d[1]), "+f"(d[2]), "+f"(d[3])
        : "r"(a[0]), "r"(a[1]), "r"(a[2]), "r"(a[3]), "r"(b0), "r"(b1));
}

// ---------------- K3: HMMA fused GEMM + bias/scale + LN + ReLU ----------------
// CTA = 128 nodes, 8 warps x 16 rows. K=256 as 2 chunks of 128.
// x=[in_norm*agg ; feat], W=[fc_w ; res_w]. bf16 hi/lo 3-term split:
//   D += Ah*Bh + Ah*Bl + Al*Bh   (fp32 accum in registers)
// smem rows padded to 272B (stride = 68 words -> row banks step by 4) ->
// conflict-free ldmatrix. smem: Ahi/Alo/Bhi/Blo 34816B each + norms = 136.5KB.
#define ROWB 272
__global__ void __launch_bounds__(256, 1)
final_kernel(const float* __restrict__ feat,
             const float* __restrict__ fc_w, const float* __restrict__ fc_b,
             const float* __restrict__ res_w,
             const float* __restrict__ ln_g, const float* __restrict__ ln_b,
             float* __restrict__ out, int nN) {
    extern __shared__ char sm[];
    const uint32_t OFF_AHI = 0, OFF_ALO = 34816;
    const uint32_t OFF_BHI = 69632, OFF_BLO = 104448;
    const uint32_t OFF_NRM = 139264;
    uint32_t sbase = smem_u32(sm);
    float* inorm_s = reinterpret_cast<float*>(sm + OFF_NRM);

    int tid = threadIdx.x;
    int lane = tid & 31;
    int warp = tid >> 5;
    int v0 = blockIdx.x * 128;
    int m0 = warp * 16;

    if (tid < 128) {
        int v = min(v0 + tid, nN - 1);
        inorm_s[tid] = rsqrtf(fmaxf(__ldg(&g_deg_in[v]), 1.f));
    }
    __syncthreads();

    // per-lane ldmatrix base addresses
    uint32_t aRow = (uint32_t)(m0 + (lane & 15)) * ROWB + (uint32_t)(lane >> 4) * 16;
    uint32_t bRow = (uint32_t)((lane & 7) + ((lane >> 3) & 1) * 8) * ROWB
                    + (uint32_t)(lane >> 4) * 16;
    uint32_t aHi = sbase + OFF_AHI + aRow, aLo = sbase + OFF_ALO + aRow;
    uint32_t bHi = sbase + OFF_BHI + bRow, bLo = sbase + OFF_BLO + bRow;

    float acc[16][4];
#pragma unroll
    for (int nt = 0; nt < 16; nt++)
#pragma unroll
        for (int e = 0; e < 4; e++) acc[nt][e] = 0.f;

    const float* ga = reinterpret_cast<const float*>(g_agg4);

    for (int c = 0; c < 2; c++) {
        // ---- stage A chunk (x cols 128c..128c+127) as bf16 hi/lo ----
        for (int i = tid; i < 4096; i += 256) {
            int m = i >> 5, j = i & 31;
            int v = min(v0 + m, nN - 1);
            float4 xv;
            if (c == 0) {
                xv = *reinterpret_cast<const float4*>(ga + (size_t)v * DIM + 4 * j);
                float t = inorm_s[m];
                xv.x *= t; xv.y *= t; xv.z *= t; xv.w *= t;
            } else {
                xv = *reinterpret_cast<const float4*>(feat + (size_t)v * DIM + 4 * j);
            }
            __nv_bfloat162 h0 = __floats2bfloat162_rn(xv.x, xv.y);
            __nv_bfloat162 h1 = __floats2bfloat162_rn(xv.z, xv.w);
            __nv_bfloat162 l0 = __floats2bfloat162_rn(xv.x - __low2float(h0),
                                                      xv.y - __high2float(h0));
            __nv_bfloat162 l1 = __floats2bfloat162_rn(xv.z - __low2float(h1),
                                                      xv.w - __high2float(h1));
            uint32_t off = (uint32_t)m * ROWB + 8 * j;
            *reinterpret_cast<__nv_bfloat162*>(sm + OFF_AHI + off)     = h0;
            *reinterpret_cast<__nv_bfloat162*>(sm + OFF_AHI + off + 4) = h1;
            *reinterpret_cast<__nv_bfloat162*>(sm + OFF_ALO + off)     = l0;
            *reinterpret_cast<__nv_bfloat162*>(sm + OFF_ALO + off + 4) = l1;
        }
        // ---- stage B chunk: W rows (K-major [k][n]) as bf16 hi/lo ----
        const float* Wc = (c == 0) ? fc_w : res_w;
        for (int i = tid; i < 4096; i += 256) {
            int k = i >> 5, j = i & 31;
            float4 wv = *reinterpret_cast<const float4*>(Wc + (size_t)k * 128 + 4 * j);
            __nv_bfloat162 h0 = __floats2bfloat162_rn(wv.x, wv.y);
            __nv_bfloat162 h1 = __floats2bfloat162_rn(wv.z, wv.w);
            __nv_bfloat162 l0 = __floats2bfloat162_rn(wv.x - __low2float(h0),
                                                      wv.y - __high2float(h0));
            __nv_bfloat162 l1 = __floats2bfloat162_rn(wv.z - __low2float(h1),
                                                      wv.w - __high2float(h1));
            uint32_t off = (uint32_t)k * ROWB + 8 * j;
            *reinterpret_cast<__nv_bfloat162*>(sm + OFF_BHI + off)     = h0;
            *reinterpret_cast<__nv_bfloat162*>(sm + OFF_BHI + off + 4) = h1;
            *reinterpret_cast<__nv_bfloat162*>(sm + OFF_BLO + off)     = l0;
            *reinterpret_cast<__nv_bfloat162*>(sm + OFF_BLO + off + 4) = l1;
        }
        __syncthreads();

        // ---- mainloop: 8 k-steps x (8 n-pair blocks x 6 MMA) — FULL N=128 ----
#pragma unroll
        for (int ks = 0; ks < 8; ks++) {
            uint32_t ah[4], al[4];
            ldmx4(ah, aHi + ks * 32);
            ldmx4(al, aLo + ks * 32);
#pragma unroll
            for (int p = 0; p < 8; p++) {
                uint32_t bh[4], bl[4];
                ldmx4t(bh, bHi + ks * (16 * ROWB) + 32 * p);
                ldmx4t(bl, bLo + ks * (16 * ROWB) + 32 * p);
                mma16816(acc[2 * p],     ah, bh[0], bh[1]);
                mma16816(acc[2 * p],     ah, bl[0], bl[1]);
                mma16816(acc[2 * p],     al, bh[0], bh[1]);
                mma16816(acc[2 * p + 1], ah, bh[2], bh[3]);
                mma16816(acc[2 * p + 1], ah, bl[2], bl[3]);
                mma16816(acc[2 * p + 1], al, bh[2], bh[3]);
            }
        }
        __syncthreads();   // smem reuse fence before next chunk staging
    }

    // ---- epilogue: bias + LayerNorm + ReLU, register-resident ----
    // acc[nt][0..1] -> row rA = m0 + lane/4,  cols nt*8 + 2*(lane%4) + {0,1}
    // acc[nt][2..3] -> row rB = rA + 8, same cols
    int rq = lane >> 2;
    int cq = (lane & 3) * 2;
    float tA = inorm_s[m0 + rq];
    float tB = inorm_s[m0 + rq + 8];

    float s1A = 0.f, s2A = 0.f, s1B = 0.f, s2B = 0.f;
#pragma unroll
    for (int nt = 0; nt < 16; nt++) {
        int col = nt * 8 + cq;
        float2 bb = *reinterpret_cast<const float2*>(fc_b + col);
        float y0 = acc[nt][0] + tA * bb.x;
        float y1 = acc[nt][1] + tA * bb.y;
        float y2 = acc[nt][2] + tB * bb.x;
        float y3 = acc[nt][3] + tB * bb.y;
        acc[nt][0] = y0; acc[nt][1] = y1; acc[nt][2] = y2; acc[nt][3] = y3;
        s1A += y0 + y1;  s2A += y0 * y0 + y1 * y1;
        s1B += y2 + y3;  s2B += y2 * y2 + y3 * y3;
    }
#pragma unroll
    for (int o = 1; o <= 2; o <<= 1) {
        s1A += __shfl_xor_sync(0xffffffffu, s1A, o);
        s2A += __shfl_xor_sync(0xffffffffu, s2A, o);
        s1B += __shfl_xor_sync(0xffffffffu, s1B, o);
        s2B += __shfl_xor_sync(0xffffffffu, s2B, o);
    }
    float muA = s1A * (1.0f / 128.0f);
    float muB = s1B * (1.0f / 128.0f);
    float rsA = rsqrtf(fmaxf(s2A * (1.0f / 128.0f) - muA * muA, 0.f) + LN_EPS);
    float rsB = rsqrtf(fmaxf(s2B * (1.0f / 128.0f) - muB * muB, 0.f) + LN_EPS);

    int rowA = v0 + m0 + rq;
    int rowB = rowA + 8;
    float* oA = out + (size_t)rowA * DIM;
    float* oB = out + (size_t)rowB * DIM;
#pragma unroll
    for (int nt = 0; nt < 16; nt++) {
        int col = nt * 8 + cq;
        float2 gg = *reinterpret_cast<const float2*>(ln_g + col);
        float2 b2 = *reinterpret_cast<const float2*>(ln_b + col);
        if (rowA < nN) {
            float2 o2;
            o2.x = fmaxf(fmaf((acc[nt][0] - muA) * rsA, gg.x, b2.x), 0.f);
            o2.y = fmaxf(fmaf((acc[nt][1] - muA) * rsA, gg.y, b2.y), 0.f);
            *reinterpret_cast<float2*>(oA + col) = o2;
        }
        if (rowB < nN) {
            float2 o2;
            o2.x = fmaxf(fmaf((acc[nt][2] - muB) * rsB, gg.x, b2.x), 0.f);
            o2.y = fmaxf(fmaf((acc[nt][3] - muB) * rsB, gg.y, b2.y), 0.f);
            *reinterpret_cast<float2*>(oB + col) = o2;
        }
    }
}

// ---------------- launcher -----------------------------------------------------
extern "C" void kernel_launch(void* const* d_in, const int* in_sizes, int n_in,
                              void* d_out, int out_size) {
    const float* feat  = (const float*)d_in[0];
    const int*   src   = (const int*)d_in[1];
    const int*   dst   = (const int*)d_in[2];
    const float* fc_w  = (const float*)d_in[3];
    const float* fc_b  = (const float*)d_in[4];
    const float* res_w = (const float*)d_in[5];
    const float* ln_g  = (const float*)d_in[6];
    const float* ln_b  = (const float*)d_in[7];
    float* out = (float*)d_out;

    int nN = in_sizes[0] / DIM;   // 50000
    int nE = in_sizes[1];         // 600000

    // K0: zero agg + degree counters
    {
        int tot = nN * (DIM / 4);
        zero_kernel<<<(tot + 255) / 256, 256>>>(nN);
    }
    // K1: degrees
    degree_kernel<<<(nE + 255) / 256, 256>>>(src, dst, nE);
    // K2: scatter-add of normalized source features (warp per 2 edges)
    {
        long long warps = ((long long)nE + 1) / 2;
        long long threads = warps * 32;
        int blocks = (int)((threads + 255) / 256);
        scatter_kernel<<<blocks, 256>>>(feat, src, dst, nE);
    }
    // K3: HMMA fused GEMM + bias + in_norm scale + residual + LN + ReLU
    {
        const int SMEM = 139776;
        cudaFuncSetAttribute(final_kernel,
                             cudaFuncAttributeMaxDynamicSharedMemorySize, SMEM);
        int blocks = (nN + 127) / 128;   // 391
        final_kernel<<<blocks, 256, SMEM>>>(feat, fc_w, fc_b, res_w, ln_g, ln_b,
                                            out, nN);
    }
}

// round 16
// speedup vs baseline: 1.5310x; 1.0219x over previous
#include <cuda_runtime.h>
#include <cuda_bf16.h>
#include <cstdint>

#define N_NODES 50000
#define N_EDGES 600000
#define DIM 128
#define LN_EPS 1e-5f

// ---------------- scratch (static device globals; no allocation) -------------
__device__ float4 g_agg4[N_NODES * (DIM / 4)];   // 25.6 MB aggregation buffer
__device__ float  g_deg_out[N_NODES];
__device__ float  g_deg_in[N_NODES];
__device__ __nv_bfloat16 g_whi[256 * 128];       // W=[fc_w;res_w] hi bf16
__device__ __nv_bfloat16 g_wlo[256 * 128];       // W lo residual bf16

// ---------------- K0: zero agg + degree counters ------------------------------
__global__ void zero_kernel(int nN) {
    int i = blockIdx.x * blockDim.x + threadIdx.x;
    int tot = nN * (DIM / 4);
    if (i < tot) g_agg4[i] = make_float4(0.f, 0.f, 0.f, 0.f);
    if (i < nN) { g_deg_out[i] = 0.f; g_deg_in[i] = 0.f; }
}

// ---------------- K0b: pre-split W into bf16 hi/lo (once) ---------------------
__global__ void wsplit_kernel(const float* __restrict__ fc_w,
                              const float* __restrict__ res_w) {
    int i = blockIdx.x * blockDim.x + threadIdx.x;   // over 8192 float4 groups
    if (i >= 8192) return;
    int k = i >> 5, j = i & 31;
    const float* Wc = (k < 128) ? (fc_w + k * 128) : (res_w + (k - 128) * 128);
    float4 wv = *reinterpret_cast<const float4*>(Wc + 4 * j);
    __nv_bfloat162 h0 = __floats2bfloat162_rn(wv.x, wv.y);
    __nv_bfloat162 h1 = __floats2bfloat162_rn(wv.z, wv.w);
    __nv_bfloat162 l0 = __floats2bfloat162_rn(wv.x - __low2float(h0),
                                              wv.y - __high2float(h0));
    __nv_bfloat162 l1 = __floats2bfloat162_rn(wv.z - __low2float(h1),
                                              wv.w - __high2float(h1));
    *reinterpret_cast<__nv_bfloat162*>(g_whi + k * 128 + 4 * j)     = h0;
    *reinterpret_cast<__nv_bfloat162*>(g_whi + k * 128 + 4 * j + 2) = h1;
    *reinterpret_cast<__nv_bfloat162*>(g_wlo + k * 128 + 4 * j)     = l0;
    *reinterpret_cast<__nv_bfloat162*>(g_wlo + k * 128 + 4 * j + 2) = l1;
}

// ---------------- K1: degrees --------------------------------------------------
__global__ void degree_kernel(const int* __restrict__ src,
                              const int* __restrict__ dst, int nE) {
    int i = blockIdx.x * blockDim.x + threadIdx.x;
    if (i < nE) {
        atomicAdd(&g_deg_out[src[i]], 1.f);
        atomicAdd(&g_deg_in[dst[i]], 1.f);
    }
}

// ---------------- K2: edge scatter (warp per 2 edges, float4 atomics) ---------
__global__ void __launch_bounds__(256)
scatter_kernel(const float* __restrict__ feat,
               const int* __restrict__ src,
               const int* __restrict__ dst, int nE) {
    int gtid = blockIdx.x * blockDim.x + threadIdx.x;
    int w = gtid >> 5;
    int lane = gtid & 31;
    int e0 = w * 2;
    if (e0 >= nE) return;
    int e1 = e0 + 1;
    bool has1 = (e1 < nE);

    int s0 = __ldg(src + e0);
    int d0 = __ldg(dst + e0);
    int s1 = has1 ? __ldg(src + e1) : s0;
    int d1 = has1 ? __ldg(dst + e1) : d0;

    float ns0 = rsqrtf(fmaxf(__ldg(&g_deg_out[s0]), 1.f));
    float ns1 = rsqrtf(fmaxf(__ldg(&g_deg_out[s1]), 1.f));

    const float4* f4 = reinterpret_cast<const float4*>(feat);
    float4 v0 = __ldcg(f4 + (size_t)s0 * 32 + lane);
    float4 v1 = __ldcg(f4 + (size_t)s1 * 32 + lane);

    v0.x *= ns0; v0.y *= ns0; v0.z *= ns0; v0.w *= ns0;
    atomicAdd(&g_agg4[(size_t)d0 * 32 + lane], v0);
    if (has1) {
        v1.x *= ns1; v1.y *= ns1; v1.z *= ns1; v1.w *= ns1;
        atomicAdd(&g_agg4[(size_t)d1 * 32 + lane], v1);
    }
}

// ================= mma.sync helpers (sm_80+ HMMA) =============================
__device__ __forceinline__ uint32_t smem_u32(const void* p) {
    uint32_t a;
    asm("{ .reg .u64 t; cvta.to.shared.u64 t, %1; cvt.u32.u64 %0, t; }"
        : "=r"(a) : "l"(p));
    return a;
}
__device__ __forceinline__ void ldmx4(uint32_t r[4], uint32_t addr) {
    asm volatile("ldmatrix.sync.aligned.m8n8.x4.shared.b16 {%0,%1,%2,%3}, [%4];"
                 : "=r"(r[0]), "=r"(r[1]), "=r"(r[2]), "=r"(r[3]) : "r"(addr));
}
__device__ __forceinline__ void ldmx4t(uint32_t r[4], uint32_t addr) {
    asm volatile("ldmatrix.sync.aligned.m8n8.x4.trans.shared.b16 {%0,%1,%2,%3}, [%4];"
                 : "=r"(r[0]), "=r"(r[1]), "=r"(r[2]), "=r"(r[3]) : "r"(addr));
}
__device__ __forceinline__ void mma16816(float* d, const uint32_t* a,
                                         uint32_t b0, uint32_t b1) {
    asm volatile(
        "mma.sync.aligned.m16n8k16.row.col.f32.bf16.bf16.f32 "
        "{%0,%1,%2,%3}, {%4,%5,%6,%7}, {%8,%9}, {%0,%1,%2,%3};"
        : "+f"(d[0]), "+f"(d[1]), "+f"(d[2]), "+f"(d[3])
        : "r"(a[0]), "r"(a[1]), "r"(a[2]), "r"(a[3]), "r"(b0), "r"(b1));
}

// ---------------- K3: HMMA fused GEMM + bias/scale + LN + ReLU ----------------
// CTA = 128 nodes, 512 threads = 16 warps: warp w -> M-tile (w&7)*16 rows,
// N-half (w>>3)*64 cols. K=256 as 2 chunks of 128. bf16 hi/lo 3-term split,
// term-major MMA order (dependency distance 8). W pre-split in gmem.
#define ROWB 272
__global__ void __launch_bounds__(512, 1)
final_kernel(const float* __restrict__ feat,
             const float* __restrict__ fc_b,
             const float* __restrict__ ln_g, const float* __restrict__ ln_b,
             float* __restrict__ out, int nN) {
    extern __shared__ char sm[];
    const uint32_t OFF_AHI = 0, OFF_ALO = 34816;
    const uint32_t OFF_BHI = 69632, OFF_BLO = 104448;
    const uint32_t OFF_NRM = 139264;   // 128 floats
    const uint32_t OFF_STAT = 139776;  // 128 rows x 2 halves x float2 = 2KB
    uint32_t sbase = smem_u32(sm);
    float* inorm_s = reinterpret_cast<float*>(sm + OFF_NRM);
    float2* stat_s = reinterpret_cast<float2*>(sm + OFF_STAT);

    int tid = threadIdx.x;
    int lane = tid & 31;
    int warp = tid >> 5;
    int mw = warp & 7;          // M-tile
    int nh = warp >> 3;         // N-half (0/1)
    int v0 = blockIdx.x * 128;
    int m0 = mw * 16;

    if (tid < 128) {
        int v = min(v0 + tid, nN - 1);
        inorm_s[tid] = rsqrtf(fmaxf(__ldg(&g_deg_in[v]), 1.f));
    }
    __syncthreads();

    uint32_t aRow = (uint32_t)(m0 + (lane & 15)) * ROWB + (uint32_t)(lane >> 4) * 16;
    uint32_t bRow = (uint32_t)((lane & 7) + ((lane >> 3) & 1) * 8) * ROWB
                    + (uint32_t)(lane >> 4) * 16 + (uint32_t)nh * 128;
    uint32_t aHi = sbase + OFF_AHI + aRow, aLo = sbase + OFF_ALO + aRow;
    uint32_t bHi = sbase + OFF_BHI + bRow, bLo = sbase + OFF_BLO + bRow;

    float acc[8][4];
#pragma unroll
    for (int nt = 0; nt < 8; nt++)
#pragma unroll
        for (int e = 0; e < 4; e++) acc[nt][e] = 0.f;

    const float* ga = reinterpret_cast<const float*>(g_agg4);

    for (int c = 0; c < 2; c++) {
        // ---- stage A chunk (x cols 128c..) as bf16 hi/lo ----
        for (int i = tid; i < 4096; i += 512) {
            int m = i >> 5, j = i & 31;
            int v = min(v0 + m, nN - 1);
            float4 xv;
            if (c == 0) {
                xv = *reinterpret_cast<const float4*>(ga + (size_t)v * DIM + 4 * j);
                float t = inorm_s[m];
                xv.x *= t; xv.y *= t; xv.z *= t; xv.w *= t;
            } else {
                xv = *reinterpret_cast<const float4*>(feat + (size_t)v * DIM + 4 * j);
            }
            __nv_bfloat162 h0 = __floats2bfloat162_rn(xv.x, xv.y);
            __nv_bfloat162 h1 = __floats2bfloat162_rn(xv.z, xv.w);
            __nv_bfloat162 l0 = __floats2bfloat162_rn(xv.x - __low2float(h0),
                                                      xv.y - __high2float(h0));
            __nv_bfloat162 l1 = __floats2bfloat162_rn(xv.z - __low2float(h1),
                                                      xv.w - __high2float(h1));
            uint32_t off = (uint32_t)m * ROWB + 8 * j;
            *reinterpret_cast<__nv_bfloat162*>(sm + OFF_AHI + off)     = h0;
            *reinterpret_cast<__nv_bfloat162*>(sm + OFF_AHI + off + 4) = h1;
            *reinterpret_cast<__nv_bfloat162*>(sm + OFF_ALO + off)     = l0;
            *reinterpret_cast<__nv_bfloat162*>(sm + OFF_ALO + off + 4) = l1;
        }
        // ---- stage B chunk: plain 16B copies of pre-split W ----
        const uint4* whiv = reinterpret_cast<const uint4*>(g_whi + c * 128 * 128);
        const uint4* wlov = reinterpret_cast<const uint4*>(g_wlo + c * 128 * 128);
        for (int i = tid; i < 2048; i += 512) {
            int k = i >> 4, j = i & 15;
            uint32_t off = (uint32_t)k * ROWB + 16 * j;
            *reinterpret_cast<uint4*>(sm + OFF_BHI + off) = __ldg(whiv + i);
            *reinterpret_cast<uint4*>(sm + OFF_BLO + off) = __ldg(wlov + i);
        }
        __syncthreads();

        // ---- mainloop: 8 k-steps; term-major MMA order ----
#pragma unroll
        for (int ks = 0; ks < 8; ks++) {
            uint32_t ah[4], al[4];
            ldmx4(ah, aHi + ks * 32);
            ldmx4(al, aLo + ks * 32);
            uint32_t bh[4][4], bl[4][4];
#pragma unroll
            for (int p = 0; p < 4; p++) {
                ldmx4t(bh[p], bHi + ks * (16 * ROWB) + 32 * p);
                ldmx4t(bl[p], bLo + ks * (16 * ROWB) + 32 * p);
            }
            // term hh
#pragma unroll
            for (int p = 0; p < 4; p++) {
                mma16816(acc[2 * p],     ah, bh[p][0], bh[p][1]);
                mma16816(acc[2 * p + 1], ah, bh[p][2], bh[p][3]);
            }
            // term hl
#pragma unroll
            for (int p = 0; p < 4; p++) {
                mma16816(acc[2 * p],     ah, bl[p][0], bl[p][1]);
                mma16816(acc[2 * p + 1], ah, bl[p][2], bl[p][3]);
            }
            // term lh
#pragma unroll
            for (int p = 0; p < 4; p++) {
                mma16816(acc[2 * p],     al, bh[p][0], bh[p][1]);
                mma16816(acc[2 * p + 1], al, bh[p][2], bh[p][3]);
            }
        }
        __syncthreads();   // smem reuse fence
    }

    // ---- epilogue: bias + split-row LN via smem stats + ReLU ----
    int rq = lane >> 2;
    int cq = (lane & 3) * 2;
    int rA = m0 + rq, rB = rA + 8;
    float tA = inorm_s[rA];
    float tB = inorm_s[rB];

    float s1A = 0.f, s2A = 0.f, s1B = 0.f, s2B = 0.f;
#pragma unroll
    for (int nt = 0; nt < 8; nt++) {
        int col = nh * 64 + nt * 8 + cq;
        float2 bb = *reinterpret_cast<const float2*>(fc_b + col);
        float y0 = acc[nt][0] + tA * bb.x;
        float y1 = acc[nt][1] + tA * bb.y;
        float y2 = acc[nt][2] + tB * bb.x;
        float y3 = acc[nt][3] + tB * bb.y;
        acc[nt][0] = y0; acc[nt][1] = y1; acc[nt][2] = y2; acc[nt][3] = y3;
        s1A += y0 + y1;  s2A += y0 * y0 + y1 * y1;
        s1B += y2 + y3;  s2B += y2 * y2 + y3 * y3;
    }
#pragma unroll
    for (int o = 1; o <= 2; o <<= 1) {
        s1A += __shfl_xor_sync(0xffffffffu, s1A, o);
        s2A += __shfl_xor_sync(0xffffffffu, s2A, o);
        s1B += __shfl_xor_sync(0xffffffffu, s1B, o);
        s2B += __shfl_xor_sync(0xffffffffu, s2B, o);
    }
    if ((lane & 3) == 0) {
        stat_s[rA * 2 + nh] = make_float2(s1A, s2A);
        stat_s[rB * 2 + nh] = make_float2(s1B, s2B);
    }
    __syncthreads();
    float2 pA0 = stat_s[rA * 2], pA1 = stat_s[rA * 2 + 1];
    float2 pB0 = stat_s[rB * 2], pB1 = stat_s[rB * 2 + 1];
    float muA = (pA0.x + pA1.x) * (1.0f / 128.0f);
    float muB = (pB0.x + pB1.x) * (1.0f / 128.0f);
    float rsA = rsqrtf(fmaxf((pA0.y + pA1.y) * (1.0f / 128.0f) - muA * muA, 0.f) + LN_EPS);
    float rsB = rsqrtf(fmaxf((pB0.y + pB1.y) * (1.0f / 128.0f) - muB * muB, 0.f) + LN_EPS);

    int rowA = v0 + rA, rowB = v0 + rB;
    float* oA = out + (size_t)rowA * DIM;
    float* oB = out + (size_t)rowB * DIM;
#pragma unroll
    for (int nt = 0; nt < 8; nt++) {
        int col = nh * 64 + nt * 8 + cq;
        float2 gg = *reinterpret_cast<const float2*>(ln_g + col);
        float2 b2 = *reinterpret_cast<const float2*>(ln_b + col);
        if (rowA < nN) {
            float2 o2;
            o2.x = fmaxf(fmaf((acc[nt][0] - muA) * rsA, gg.x, b2.x), 0.f);
            o2.y = fmaxf(fmaf((acc[nt][1] - muA) * rsA, gg.y, b2.y), 0.f);
            *reinterpret_cast<float2*>(oA + col) = o2;
        }
        if (rowB < nN) {
            float2 o2;
            o2.x = fmaxf(fmaf((acc[nt][2] - muB) * rsB, gg.x, b2.x), 0.f);
            o2.y = fmaxf(fmaf((acc[nt][3] - muB) * rsB, gg.y, b2.y), 0.f);
            *reinterpret_cast<float2*>(oB + col) = o2;
        }
    }
}

// ---------------- launcher -----------------------------------------------------
extern "C" void kernel_launch(void* const* d_in, const int* in_sizes, int n_in,
                              void* d_out, int out_size) {
    const float* feat  = (const float*)d_in[0];
    const int*   src   = (const int*)d_in[1];
    const int*   dst   = (const int*)d_in[2];
    const float* fc_w  = (const float*)d_in[3];
    const float* fc_b  = (const float*)d_in[4];
    const float* res_w = (const float*)d_in[5];
    const float* ln_g  = (const float*)d_in[6];
    const float* ln_b  = (const float*)d_in[7];
    float* out = (float*)d_out;

    int nN = in_sizes[0] / DIM;   // 50000
    int nE = in_sizes[1];         // 600000

    // K0: zero agg + degree counters; K0b: pre-split W
    {
        int tot = nN * (DIM / 4);
        zero_kernel<<<(tot + 255) / 256, 256>>>(nN);
        wsplit_kernel<<<32, 256>>>(fc_w, res_w);
    }
    // K1: degrees
    degree_kernel<<<(nE + 255) / 256, 256>>>(src, dst, nE);
    // K2: scatter-add of normalized source features (warp per 2 edges)
    {
        long long warps = ((long long)nE + 1) / 2;
        long long threads = warps * 32;
        int blocks = (int)((threads + 255) / 256);
        scatter_kernel<<<blocks, 256>>>(feat, src, dst, nE);
    }
    // K3: HMMA fused GEMM + bias + in_norm scale + residual + LN + ReLU
    {
        const int SMEM = 141824;
        cudaFuncSetAttribute(final_kernel,
                             cudaFuncAttributeMaxDynamicSharedMemorySize, SMEM);
        int blocks = (nN + 127) / 128;   // 391
        final_kernel<<<blocks, 512, SMEM>>>(feat, fc_b, ln_g, ln_b, out, nN);
    }
}